// round 1
// baseline (speedup 1.0000x reference)
#include <cuda_runtime.h>
#include <cuda_bf16.h>
#include <math.h>

#define B_   64
#define S_   577
#define D_   768
#define H_   12
#define DH_  64
#define FF_  3072
#define NT_  (B_ * S_)          // 36928 tokens

// ---------------- scratch (__device__ globals: allocation-rule-safe) ----------------
__device__ float g_h[(size_t)NT_ * D_];            // LN output (reused for LN1 and LN2)
__device__ float g_qkv[(size_t)NT_ * 3 * D_];      // [token, 2304]: q | k | v, each col h*64+e
__device__ float g_scores[(size_t)B_ * H_ * S_ * S_]; // [bh, S, S]
__device__ float g_attn[(size_t)NT_ * D_];         // [token, h*64+e]
__device__ float g_ff[(size_t)NT_ * FF_];          // MLP intermediate
__device__ float g_wqkv[(size_t)D_ * 3 * D_];      // packed [768, 2304]
__device__ float g_bqkv[3 * D_];

// ---------------- helpers ----------------
__device__ __forceinline__ float gelu_tanh(float x) {
    const float c = 0.7978845608028654f;
    float x3 = x * x * x;
    return 0.5f * x * (1.0f + tanhf(c * (x + 0.044715f * x3)));
}

// ---------------- pack per-head QKV weights into fused [D, 2304] ----------------
__global__ void pack_qkv_kernel(const float* __restrict__ Wq, const float* __restrict__ Wk,
                                const float* __restrict__ Wv, const float* __restrict__ bq,
                                const float* __restrict__ bk, const float* __restrict__ bv) {
    size_t idx = (size_t)blockIdx.x * blockDim.x + threadIdx.x;
    size_t total = (size_t)D_ * 3 * D_;
    if (idx >= total) return;
    int d  = (int)(idx / (3 * D_));
    int j  = (int)(idx % (3 * D_));
    int sel = j / D_;
    int jj  = j % D_;
    int h = jj / DH_;
    int e = jj % DH_;
    const float* W = (sel == 0) ? Wq : (sel == 1) ? Wk : Wv;
    g_wqkv[idx] = W[((size_t)h * D_ + d) * DH_ + e];
    if (d == 0) {
        const float* bb = (sel == 0) ? bq : (sel == 1) ? bk : bv;
        g_bqkv[j] = bb[jj];
    }
}

// ---------------- LayerNorm: one block per token, 256 threads, 3 elems/thread ----------------
__global__ __launch_bounds__(256) void ln_kernel(const float* __restrict__ x,
                                                 const float* __restrict__ g,
                                                 const float* __restrict__ bet,
                                                 float* __restrict__ out) {
    int t = blockIdx.x;
    const float* xr = x + (size_t)t * D_;
    float* orow = out + (size_t)t * D_;
    int tid = threadIdx.x;
    float v0 = xr[tid], v1 = xr[tid + 256], v2 = xr[tid + 512];
    float s  = v0 + v1 + v2;
    float ss = v0 * v0 + v1 * v1 + v2 * v2;
    #pragma unroll
    for (int o = 16; o > 0; o >>= 1) {
        s  += __shfl_xor_sync(0xffffffffu, s, o);
        ss += __shfl_xor_sync(0xffffffffu, ss, o);
    }
    __shared__ float sh[16];
    __shared__ float mb[2];
    int w = tid >> 5, lane = tid & 31;
    if (lane == 0) { sh[w] = s; sh[w + 8] = ss; }
    __syncthreads();
    if (tid == 0) {
        float S1 = 0.f, S2 = 0.f;
        #pragma unroll
        for (int i = 0; i < 8; i++) { S1 += sh[i]; S2 += sh[i + 8]; }
        float mean = S1 * (1.0f / D_);
        float var  = S2 * (1.0f / D_) - mean * mean;
        mb[0] = mean;
        mb[1] = rsqrtf(var + 1e-6f);
    }
    __syncthreads();
    float mean = mb[0], rstd = mb[1];
    orow[tid]       = (v0 - mean) * rstd * g[tid]       + bet[tid];
    orow[tid + 256] = (v1 - mean) * rstd * g[tid + 256] + bet[tid + 256];
    orow[tid + 512] = (v2 - mean) * rstd * g[tid + 512] + bet[tid + 512];
}

// ---------------- Generic SGEMM: C[M,N] = A[M,K] * B[K,N] + bias (+epilogue) ----------------
// EPI: 0 = bias, 1 = bias + gelu, 2 = bias + residual
#define BM 128
#define BN 128
#define BK 16
template <int EPI>
__global__ __launch_bounds__(256) void sgemm_kernel(const float* __restrict__ A,
                                                    const float* __restrict__ Bw,
                                                    const float* __restrict__ bias,
                                                    const float* __restrict__ res,
                                                    float* __restrict__ C,
                                                    int M, int N, int K) {
    __shared__ float As[BK][BM];
    __shared__ float Bs[BK][BN];
    int tid = threadIdx.x;
    int bx = blockIdx.x, by = blockIdx.y;
    int tx = tid & 15, ty = tid >> 4;
    int rowC = by * BM + ty * 8;
    int colC = bx * BN + tx * 8;

    float acc[8][8];
    #pragma unroll
    for (int i = 0; i < 8; i++)
        #pragma unroll
        for (int j = 0; j < 8; j++) acc[i][j] = 0.f;

    int aRow = tid >> 2;          // 0..63
    int aCol = (tid & 3) * 4;     // 0,4,8,12
    int bRow = tid >> 5;          // 0..7
    int bCol = (tid & 31) * 4;    // 0..124

    for (int k0 = 0; k0 < K; k0 += BK) {
        #pragma unroll
        for (int i = 0; i < 2; i++) {
            int r = by * BM + aRow + i * 64;
            float4 av = (r < M) ? *(const float4*)&A[(size_t)r * K + k0 + aCol]
                                : make_float4(0.f, 0.f, 0.f, 0.f);
            As[aCol + 0][aRow + i * 64] = av.x;
            As[aCol + 1][aRow + i * 64] = av.y;
            As[aCol + 2][aRow + i * 64] = av.z;
            As[aCol + 3][aRow + i * 64] = av.w;
        }
        #pragma unroll
        for (int i = 0; i < 2; i++) {
            int r = k0 + bRow + i * 8;
            float4 bv = *(const float4*)&Bw[(size_t)r * N + bx * BN + bCol];
            *(float4*)&Bs[bRow + i * 8][bCol] = bv;
        }
        __syncthreads();
        #pragma unroll
        for (int kk = 0; kk < BK; kk++) {
            float af[8], bf[8];
            #pragma unroll
            for (int i = 0; i < 8; i++) af[i] = As[kk][ty * 8 + i];
            #pragma unroll
            for (int j = 0; j < 8; j++) bf[j] = Bs[kk][tx * 8 + j];
            #pragma unroll
            for (int i = 0; i < 8; i++)
                #pragma unroll
                for (int j = 0; j < 8; j++) acc[i][j] += af[i] * bf[j];
        }
        __syncthreads();
    }

    #pragma unroll
    for (int i = 0; i < 8; i++) {
        int r = rowC + i;
        if (r >= M) continue;
        #pragma unroll
        for (int j = 0; j < 8; j++) {
            int c = colC + j;
            float v = acc[i][j] + bias[c];
            if (EPI == 1) v = gelu_tanh(v);
            else if (EPI == 2) v += res[(size_t)r * N + c];
            C[(size_t)r * N + c] = v;
        }
    }
}

// ---------------- scores[bh,i,j] = 0.125 * sum_e q[i,e]*k[j,e] ----------------
__global__ __launch_bounds__(256) void score_kernel(const float* __restrict__ qkv,
                                                    float* __restrict__ scores) {
    int bh = blockIdx.z;
    int b = bh / H_, h = bh % H_;
    int it = blockIdx.y, jt = blockIdx.x;
    __shared__ float qs[64][65];
    __shared__ float ks[64][65];
    int tid = threadIdx.x;
    int lr = tid >> 2;              // 0..63
    int lc = (tid & 3) * 16;        // 0,16,32,48

    {
        int sq = it * 64 + lr;
        int sk = jt * 64 + lr;
        const float* qbase = (sq < S_) ? &qkv[((size_t)(b * S_ + sq)) * (3 * D_) + h * DH_] : nullptr;
        const float* kbase = (sk < S_) ? &qkv[((size_t)(b * S_ + sk)) * (3 * D_) + D_ + h * DH_] : nullptr;
        #pragma unroll
        for (int c = 0; c < 16; c += 4) {
            float4 qv = qbase ? *(const float4*)&qbase[lc + c] : make_float4(0.f,0.f,0.f,0.f);
            float4 kv = kbase ? *(const float4*)&kbase[lc + c] : make_float4(0.f,0.f,0.f,0.f);
            qs[lr][lc + c + 0] = qv.x; qs[lr][lc + c + 1] = qv.y;
            qs[lr][lc + c + 2] = qv.z; qs[lr][lc + c + 3] = qv.w;
            ks[lr][lc + c + 0] = kv.x; ks[lr][lc + c + 1] = kv.y;
            ks[lr][lc + c + 2] = kv.z; ks[lr][lc + c + 3] = kv.w;
        }
    }
    __syncthreads();

    int tx = tid & 15, ty = tid >> 4;
    int i0 = ty * 4, j0 = tx * 4;
    float acc[4][4];
    #pragma unroll
    for (int i = 0; i < 4; i++)
        #pragma unroll
        for (int j = 0; j < 4; j++) acc[i][j] = 0.f;

    #pragma unroll 8
    for (int e = 0; e < 64; e++) {
        float af[4], bf[4];
        #pragma unroll
        for (int i = 0; i < 4; i++) af[i] = qs[i0 + i][e];
        #pragma unroll
        for (int j = 0; j < 4; j++) bf[j] = ks[j0 + j][e];
        #pragma unroll
        for (int i = 0; i < 4; i++)
            #pragma unroll
            for (int j = 0; j < 4; j++) acc[i][j] += af[i] * bf[j];
    }

    #pragma unroll
    for (int i = 0; i < 4; i++) {
        int gi = it * 64 + i0 + i;
        if (gi >= S_) continue;
        #pragma unroll
        for (int j = 0; j < 4; j++) {
            int gj = jt * 64 + j0 + j;
            if (gj >= S_) continue;
            scores[((size_t)bh * S_ + gi) * S_ + gj] = acc[i][j] * 0.125f;
        }
    }
}

// ---------------- softmax over rows of g_scores (len S) ----------------
__global__ __launch_bounds__(128) void softmax_kernel(float* __restrict__ sc) {
    size_t row = blockIdx.x;
    float* p = sc + row * S_;
    int tid = threadIdx.x;
    float v[5];
    float m = -1e30f;
    #pragma unroll
    for (int i = 0; i < 5; i++) {
        int idx = tid + i * 128;
        v[i] = (idx < S_) ? p[idx] : -1e30f;
        m = fmaxf(m, v[i]);
    }
    __shared__ float sh[8];
    #pragma unroll
    for (int o = 16; o > 0; o >>= 1) m = fmaxf(m, __shfl_xor_sync(0xffffffffu, m, o));
    if ((tid & 31) == 0) sh[tid >> 5] = m;
    __syncthreads();
    m = fmaxf(fmaxf(sh[0], sh[1]), fmaxf(sh[2], sh[3]));

    float s = 0.f;
    #pragma unroll
    for (int i = 0; i < 5; i++) { v[i] = __expf(v[i] - m); s += v[i]; }
    #pragma unroll
    for (int o = 16; o > 0; o >>= 1) s += __shfl_xor_sync(0xffffffffu, s, o);
    __syncthreads();
    if ((tid & 31) == 0) sh[4 + (tid >> 5)] = s;
    __syncthreads();
    s = sh[4] + sh[5] + sh[6] + sh[7];
    float inv = 1.0f / s;
    #pragma unroll
    for (int i = 0; i < 5; i++) {
        int idx = tid + i * 128;
        if (idx < S_) p[idx] = v[i] * inv;
    }
}

// ---------------- attn[b,s,h,e] = sum_t probs[bh,s,t] * v[b,t,h,e] ----------------
__global__ __launch_bounds__(256) void pv_kernel(const float* __restrict__ scores,
                                                 const float* __restrict__ qkv,
                                                 float* __restrict__ attn) {
    int bh = blockIdx.z;
    int b = bh / H_, h = bh % H_;
    int it = blockIdx.x;
    __shared__ float Ps[64][33];
    __shared__ float Vs[32][68];
    int tid = threadIdx.x;
    int tx = tid & 15, ty = tid >> 4;
    int i0 = ty * 4, j0 = tx * 4;
    float acc[4][4];
    #pragma unroll
    for (int i = 0; i < 4; i++)
        #pragma unroll
        for (int j = 0; j < 4; j++) acc[i][j] = 0.f;

    int pr = tid >> 3;              // 0..31
    int pc = (tid & 7) * 4;         // 0..28
    int vr = tid >> 3;              // 0..31
    int vc = (tid & 7) * 8;         // 0..56

    for (int k0 = 0; k0 < S_; k0 += 32) {
        // load P tile [64 x 32]
        #pragma unroll
        for (int pass = 0; pass < 2; pass++) {
            int r = pr + pass * 32;
            int grow = it * 64 + r;
            #pragma unroll
            for (int c = 0; c < 4; c++) {
                int gk = k0 + pc + c;
                Ps[r][pc + c] = (grow < S_ && gk < S_)
                    ? scores[((size_t)bh * S_ + grow) * S_ + gk] : 0.f;
            }
        }
        // load V tile [32 x 64]
        {
            int gk = k0 + vr;
            if (gk < S_) {
                const float* vbase = &qkv[((size_t)(b * S_ + gk)) * (3 * D_) + 2 * D_ + h * DH_];
                float4 a = *(const float4*)&vbase[vc];
                float4 c2 = *(const float4*)&vbase[vc + 4];
                *(float4*)&Vs[vr][vc]     = a;
                *(float4*)&Vs[vr][vc + 4] = c2;
            } else {
                *(float4*)&Vs[vr][vc]     = make_float4(0.f,0.f,0.f,0.f);
                *(float4*)&Vs[vr][vc + 4] = make_float4(0.f,0.f,0.f,0.f);
            }
        }
        __syncthreads();
        #pragma unroll 8
        for (int kk = 0; kk < 32; kk++) {
            float af[4], bf[4];
            #pragma unroll
            for (int i = 0; i < 4; i++) af[i] = Ps[i0 + i][kk];
            #pragma unroll
            for (int j = 0; j < 4; j++) bf[j] = Vs[kk][j0 + j];
            #pragma unroll
            for (int i = 0; i < 4; i++)
                #pragma unroll
                for (int j = 0; j < 4; j++) acc[i][j] += af[i] * bf[j];
        }
        __syncthreads();
    }

    #pragma unroll
    for (int i = 0; i < 4; i++) {
        int gi = it * 64 + i0 + i;
        if (gi >= S_) continue;
        float* orow = &attn[((size_t)(b * S_ + gi)) * D_ + h * DH_];
        #pragma unroll
        for (int j = 0; j < 4; j++) orow[j0 + j] = acc[i][j];
    }
}

// ---------------- launch ----------------
extern "C" void kernel_launch(void* const* d_in, const int* in_sizes, int n_in,
                              void* d_out, int out_size) {
    const float* x     = (const float*)d_in[0];
    const float* ln1_g = (const float*)d_in[1];
    const float* ln1_b = (const float*)d_in[2];
    const float* Wq    = (const float*)d_in[3];
    const float* bq    = (const float*)d_in[4];
    const float* Wk    = (const float*)d_in[5];
    const float* bk    = (const float*)d_in[6];
    const float* Wv    = (const float*)d_in[7];
    const float* bv    = (const float*)d_in[8];
    const float* Wo    = (const float*)d_in[9];
    const float* bo    = (const float*)d_in[10];
    const float* ln2_g = (const float*)d_in[11];
    const float* ln2_b = (const float*)d_in[12];
    const float* W1    = (const float*)d_in[13];
    const float* b1    = (const float*)d_in[14];
    const float* W2    = (const float*)d_in[15];
    const float* b2    = (const float*)d_in[16];
    float* out = (float*)d_out;

    float* h_p;      cudaGetSymbolAddress((void**)&h_p, g_h);
    float* qkv_p;    cudaGetSymbolAddress((void**)&qkv_p, g_qkv);
    float* scores_p; cudaGetSymbolAddress((void**)&scores_p, g_scores);
    float* attn_p;   cudaGetSymbolAddress((void**)&attn_p, g_attn);
    float* ff_p;     cudaGetSymbolAddress((void**)&ff_p, g_ff);
    float* wqkv_p;   cudaGetSymbolAddress((void**)&wqkv_p, g_wqkv);
    float* bqkv_p;   cudaGetSymbolAddress((void**)&bqkv_p, g_bqkv);

    // 1. pack fused QKV weights
    {
        size_t total = (size_t)D_ * 3 * D_;
        int blocks = (int)((total + 255) / 256);
        pack_qkv_kernel<<<blocks, 256>>>(Wq, Wk, Wv, bq, bk, bv);
    }
    // 2. LN1
    ln_kernel<<<NT_, 256>>>(x, ln1_g, ln1_b, h_p);
    // 3. fused QKV GEMM: [NT,768] x [768,2304]
    {
        dim3 grid(3 * D_ / BN, (NT_ + BM - 1) / BM);
        sgemm_kernel<0><<<grid, 256>>>(h_p, wqkv_p, bqkv_p, nullptr, qkv_p, NT_, 3 * D_, D_);
    }
    // 4. scores = q k^T / 8
    {
        dim3 grid((S_ + 63) / 64, (S_ + 63) / 64, B_ * H_);
        score_kernel<<<grid, 256>>>(qkv_p, scores_p);
    }
    // 5. softmax
    softmax_kernel<<<B_ * H_ * S_, 128>>>(scores_p);
    // 6. attn = probs @ v
    {
        dim3 grid((S_ + 63) / 64, 1, B_ * H_);
        pv_kernel<<<grid, 256>>>(scores_p, qkv_p, attn_p);
    }
    // 7. x2 = x + attn @ Wo + bo   -> out
    {
        dim3 grid(D_ / BN, (NT_ + BM - 1) / BM);
        sgemm_kernel<2><<<grid, 256>>>(attn_p, Wo, bo, x, out, NT_, D_, D_);
    }
    // 8. LN2 on x2
    ln_kernel<<<NT_, 256>>>(out, ln2_g, ln2_b, h_p);
    // 9. ff = gelu(m @ W1 + b1)
    {
        dim3 grid(FF_ / BN, (NT_ + BM - 1) / BM);
        sgemm_kernel<1><<<grid, 256>>>(h_p, W1, b1, nullptr, ff_p, NT_, FF_, D_);
    }
    // 10. out = x2 + ff @ W2 + b2
    {
        dim3 grid(D_ / BN, (NT_ + BM - 1) / BM);
        sgemm_kernel<2><<<grid, 256>>>(ff_p, W2, b2, out, out, NT_, D_, FF_);
    }
}

// round 3
// speedup vs baseline: 1.2107x; 1.2107x over previous
#include <cuda_runtime.h>
#include <cuda_bf16.h>
#include <mma.h>
#include <math.h>

using namespace nvcuda;

#define B_   64
#define S_   577
#define SP_  580                 // padded scores row stride (580*4B = 16B-aligned rows)
#define D_   768
#define H_   12
#define DH_  64
#define FF_  3072
#define NT_  (B_ * S_)          // 36928 tokens

// ---------------- scratch (__device__ globals: allocation-rule-safe) ----------------
__device__ float g_h[(size_t)NT_ * D_];
__device__ float g_qkv[(size_t)NT_ * 3 * D_];
__device__ float g_scores[(size_t)B_ * H_ * S_ * SP_];
__device__ float g_attn[(size_t)NT_ * D_];
__device__ float g_ff[(size_t)NT_ * FF_];
__device__ float g_wqkv[(size_t)D_ * 3 * D_];
__device__ float g_bqkv[3 * D_];

// ---------------- helpers ----------------
__device__ __forceinline__ float gelu_tanh(float x) {
    const float c = 0.7978845608028654f;
    float x3 = x * x * x;
    return 0.5f * x * (1.0f + tanhf(c * (x + 0.044715f * x3)));
}

__device__ __forceinline__ void cp_async16(float* s, const float* g, bool pred) {
    unsigned saddr = (unsigned)__cvta_generic_to_shared(s);
    int sz = pred ? 16 : 0;
    asm volatile("cp.async.cg.shared.global [%0], [%1], 16, %2;\n"
                 :: "r"(saddr), "l"(g), "r"(sz));
}
__device__ __forceinline__ void cp_commit() { asm volatile("cp.async.commit_group;\n"); }
template <int N>
__device__ __forceinline__ void cp_wait() { asm volatile("cp.async.wait_group %0;\n" :: "n"(N)); }

// ---------------- pack per-head QKV weights into fused [D, 2304] ----------------
__global__ void pack_qkv_kernel(const float* __restrict__ Wq, const float* __restrict__ Wk,
                                const float* __restrict__ Wv, const float* __restrict__ bq,
                                const float* __restrict__ bk, const float* __restrict__ bv) {
    size_t idx = (size_t)blockIdx.x * blockDim.x + threadIdx.x;
    size_t total = (size_t)D_ * 3 * D_;
    if (idx >= total) return;
    int d  = (int)(idx / (3 * D_));
    int j  = (int)(idx % (3 * D_));
    int sel = j / D_;
    int jj  = j % D_;
    int h = jj / DH_;
    int e = jj % DH_;
    const float* W = (sel == 0) ? Wq : (sel == 1) ? Wk : Wv;
    g_wqkv[idx] = W[((size_t)h * D_ + d) * DH_ + e];
    if (d == 0) {
        const float* bb = (sel == 0) ? bq : (sel == 1) ? bk : bv;
        g_bqkv[j] = bb[jj];
    }
}

// ---------------- LayerNorm ----------------
__global__ __launch_bounds__(256) void ln_kernel(const float* __restrict__ x,
                                                 const float* __restrict__ g,
                                                 const float* __restrict__ bet,
                                                 float* __restrict__ out) {
    int t = blockIdx.x;
    const float* xr = x + (size_t)t * D_;
    float* orow = out + (size_t)t * D_;
    int tid = threadIdx.x;
    float v0 = xr[tid], v1 = xr[tid + 256], v2 = xr[tid + 512];
    float s  = v0 + v1 + v2;
    float ss = v0 * v0 + v1 * v1 + v2 * v2;
    #pragma unroll
    for (int o = 16; o > 0; o >>= 1) {
        s  += __shfl_xor_sync(0xffffffffu, s, o);
        ss += __shfl_xor_sync(0xffffffffu, ss, o);
    }
    __shared__ float sh[16];
    __shared__ float mb[2];
    int w = tid >> 5, lane = tid & 31;
    if (lane == 0) { sh[w] = s; sh[w + 8] = ss; }
    __syncthreads();
    if (tid == 0) {
        float S1 = 0.f, S2 = 0.f;
        #pragma unroll
        for (int i = 0; i < 8; i++) { S1 += sh[i]; S2 += sh[i + 8]; }
        float mean = S1 * (1.0f / D_);
        float var  = S2 * (1.0f / D_) - mean * mean;
        mb[0] = mean;
        mb[1] = rsqrtf(var + 1e-6f);
    }
    __syncthreads();
    float mean = mb[0], rstd = mb[1];
    orow[tid]       = (v0 - mean) * rstd * g[tid]       + bet[tid];
    orow[tid + 256] = (v1 - mean) * rstd * g[tid + 256] + bet[tid + 256];
    orow[tid + 512] = (v2 - mean) * rstd * g[tid + 512] + bet[tid + 512];
}

// ---------------- tf32 tensor-core SGEMM ----------------
// C[M,N] = A[M,K] * B[K,N] (+bias, EPI: 0=bias, 1=bias+gelu, 2=bias+residual)
// Tiles: 128x128x32, 256 threads (8 warps, 4x2), warp tile 32x64.
#define GBM 128
#define GBN 128
#define GBK 32
#define A_LD 36
#define B_LD 132
#define ASZ (GBM * A_LD)   // 4608 floats / buffer
#define BSZ (GBK * B_LD)   // 4224 floats / buffer
#define GEMM_SMEM_FLOATS (2 * ASZ + 2 * BSZ + 8 * 320)
#define GEMM_SMEM_BYTES  (GEMM_SMEM_FLOATS * 4)

template <int EPI>
__global__ __launch_bounds__(256) void sgemm_tc(const float* __restrict__ A,
                                                const float* __restrict__ Bw,
                                                const float* __restrict__ bias,
                                                const float* __restrict__ res,
                                                float* __restrict__ C,
                                                int M, int N, int K) {
    extern __shared__ float dsm[];
    float* As    = dsm;
    float* Bs    = dsm + 2 * ASZ;
    float* stage = dsm + 2 * ASZ + 2 * BSZ;

    int tid = threadIdx.x;
    int wid = tid >> 5, lane = tid & 31;
    int warp_m = wid & 3;      // 4 warps * 32 rows
    int warp_n = wid >> 2;     // 2 warps * 64 cols
    int blockM = blockIdx.y * GBM;
    int blockN = blockIdx.x * GBN;

    // load mappings
    int aRow = tid >> 3;          // 0..31 (+32 per pass, 4 passes)
    int aCol = (tid & 7) * 4;     // 0..28
    int bRow = tid >> 5;          // 0..7 (+8 per pass, 4 passes)
    int bCol = (tid & 31) * 4;    // 0..124

    int nk = K / GBK;

    auto issue_tile = [&](int t, int buf) {
        int k0 = t * GBK;
        float* Ad = As + buf * ASZ;
        float* Bd = Bs + buf * BSZ;
        #pragma unroll
        for (int p = 0; p < 4; p++) {
            int r = aRow + p * 32;
            bool ok = (blockM + r) < M;
            const float* gp = A + (size_t)(ok ? (blockM + r) : 0) * K + k0 + aCol;
            cp_async16(Ad + r * A_LD + aCol, gp, ok);
        }
        #pragma unroll
        for (int p = 0; p < 4; p++) {
            int r = bRow + p * 8;
            const float* gp = Bw + (size_t)(k0 + r) * N + blockN + bCol;
            cp_async16(Bd + r * B_LD + bCol, gp, true);
        }
    };

    wmma::fragment<wmma::accumulator, 16, 16, 8, float> acc[2][4];
    #pragma unroll
    for (int i = 0; i < 2; i++)
        #pragma unroll
        for (int j = 0; j < 4; j++) wmma::fill_fragment(acc[i][j], 0.0f);

    issue_tile(0, 0);
    cp_commit();

    for (int t = 0; t < nk; t++) {
        int buf = t & 1;
        if (t + 1 < nk) issue_tile(t + 1, buf ^ 1);
        cp_commit();
        cp_wait<1>();
        __syncthreads();

        float* Ab = As + buf * ASZ;
        float* Bb = Bs + buf * BSZ;
        #pragma unroll
        for (int ks = 0; ks < 4; ks++) {
            wmma::fragment<wmma::matrix_a, 16, 16, 8, wmma::precision::tf32, wmma::row_major> af[2];
            wmma::fragment<wmma::matrix_b, 16, 16, 8, wmma::precision::tf32, wmma::row_major> bf[4];
            #pragma unroll
            for (int i = 0; i < 2; i++) {
                wmma::load_matrix_sync(af[i], Ab + (warp_m * 32 + i * 16) * A_LD + ks * 8, A_LD);
                #pragma unroll
                for (int e = 0; e < af[i].num_elements; e++)
                    af[i].x[e] = wmma::__float_to_tf32(af[i].x[e]);
            }
            #pragma unroll
            for (int j = 0; j < 4; j++) {
                wmma::load_matrix_sync(bf[j], Bb + (ks * 8) * B_LD + warp_n * 64 + j * 16, B_LD);
                #pragma unroll
                for (int e = 0; e < bf[j].num_elements; e++)
                    bf[j].x[e] = wmma::__float_to_tf32(bf[j].x[e]);
            }
            #pragma unroll
            for (int i = 0; i < 2; i++)
                #pragma unroll
                for (int j = 0; j < 4; j++)
                    wmma::mma_sync(acc[i][j], af[i], bf[j], acc[i][j]);
        }
        __syncthreads();
    }

    // epilogue via per-warp 16x16 stage
    float* st = stage + wid * 320;
    int r  = lane >> 1;
    int c0 = (lane & 1) * 8;
    #pragma unroll
    for (int i = 0; i < 2; i++) {
        #pragma unroll
        for (int j = 0; j < 4; j++) {
            wmma::store_matrix_sync(st, acc[i][j], 20, wmma::mem_row_major);
            __syncwarp();
            int grow = blockM + warp_m * 32 + i * 16 + r;
            int gcol = blockN + warp_n * 64 + j * 16 + c0;
            if (grow < M) {
                #pragma unroll
                for (int cc = 0; cc < 8; cc++) {
                    float v = st[r * 20 + c0 + cc] + bias[gcol + cc];
                    if (EPI == 1) v = gelu_tanh(v);
                    else if (EPI == 2) v += res[(size_t)grow * N + gcol + cc];
                    C[(size_t)grow * N + gcol + cc] = v;
                }
            }
            __syncwarp();
        }
    }
}

// ---------------- scores = q k^T / 8 : tf32 wmma, 64x64 tiles, K=64 ----------------
__global__ __launch_bounds__(128) void score_kernel(const float* __restrict__ qkv,
                                                    float* __restrict__ scores) {
    __shared__ float qs[64 * 68];
    __shared__ float ks[64 * 68];
    __shared__ float stage[4 * 320];
    int bh = blockIdx.z;
    int b = bh / H_, h = bh % H_;
    int it = blockIdx.y, jt = blockIdx.x;
    int tid = threadIdx.x;
    int wid = tid >> 5, lane = tid & 31;

    // load q[64][64], k[64][64]
    int lr = tid >> 1;
    int lc0 = (tid & 1) * 32;
    {
        int sq = it * 64 + lr;
        int sk = jt * 64 + lr;
        const float* qp = &qkv[((size_t)(b * S_ + (sq < S_ ? sq : 0))) * (3 * D_) + h * DH_];
        const float* kp = &qkv[((size_t)(b * S_ + (sk < S_ ? sk : 0))) * (3 * D_) + D_ + h * DH_];
        bool qok = sq < S_, kok = sk < S_;
        #pragma unroll
        for (int i = 0; i < 8; i++) {
            int c = lc0 + i * 4;
            float4 qv = qok ? *(const float4*)&qp[c] : make_float4(0.f, 0.f, 0.f, 0.f);
            float4 kv = kok ? *(const float4*)&kp[c] : make_float4(0.f, 0.f, 0.f, 0.f);
            *(float4*)&qs[lr * 68 + c] = qv;
            *(float4*)&ks[lr * 68 + c] = kv;
        }
    }
    __syncthreads();

    wmma::fragment<wmma::accumulator, 16, 16, 8, float> acc[4];
    #pragma unroll
    for (int j = 0; j < 4; j++) wmma::fill_fragment(acc[j], 0.0f);

    int i0 = wid * 16;
    #pragma unroll
    for (int kk = 0; kk < 8; kk++) {
        wmma::fragment<wmma::matrix_a, 16, 16, 8, wmma::precision::tf32, wmma::row_major> af;
        wmma::load_matrix_sync(af, qs + i0 * 68 + kk * 8, 68);
        #pragma unroll
        for (int e = 0; e < af.num_elements; e++) af.x[e] = wmma::__float_to_tf32(af.x[e]);
        #pragma unroll
        for (int j = 0; j < 4; j++) {
            wmma::fragment<wmma::matrix_b, 16, 16, 8, wmma::precision::tf32, wmma::col_major> bf;
            wmma::load_matrix_sync(bf, ks + (j * 16) * 68 + kk * 8, 68);
            #pragma unroll
            for (int e = 0; e < bf.num_elements; e++) bf.x[e] = wmma::__float_to_tf32(bf.x[e]);
            wmma::mma_sync(acc[j], af, bf, acc[j]);
        }
    }

    float* st = stage + wid * 320;
    int r = lane >> 1, c0 = (lane & 1) * 8;
    #pragma unroll
    for (int j = 0; j < 4; j++) {
        #pragma unroll
        for (int e = 0; e < acc[j].num_elements; e++) acc[j].x[e] *= 0.125f;
        wmma::store_matrix_sync(st, acc[j], 20, wmma::mem_row_major);
        __syncwarp();
        int gi = it * 64 + i0 + r;
        if (gi < S_) {
            #pragma unroll
            for (int cc = 0; cc < 8; cc++) {
                int gj = jt * 64 + j * 16 + c0 + cc;
                if (gj < S_) scores[((size_t)bh * S_ + gi) * SP_ + gj] = st[r * 20 + c0 + cc];
            }
        }
        __syncwarp();
    }
}

// ---------------- softmax over rows (len S, stride SP_) ----------------
__global__ __launch_bounds__(128) void softmax_kernel(float* __restrict__ sc) {
    size_t row = blockIdx.x;
    float* p = sc + row * SP_;
    int tid = threadIdx.x;
    float v[5];
    float m = -1e30f;
    #pragma unroll
    for (int i = 0; i < 5; i++) {
        int idx = tid + i * 128;
        v[i] = (idx < S_) ? p[idx] : -1e30f;
        m = fmaxf(m, v[i]);
    }
    __shared__ float sh[8];
    #pragma unroll
    for (int o = 16; o > 0; o >>= 1) m = fmaxf(m, __shfl_xor_sync(0xffffffffu, m, o));
    if ((tid & 31) == 0) sh[tid >> 5] = m;
    __syncthreads();
    m = fmaxf(fmaxf(sh[0], sh[1]), fmaxf(sh[2], sh[3]));

    float s = 0.f;
    #pragma unroll
    for (int i = 0; i < 5; i++) { v[i] = __expf(v[i] - m); s += v[i]; }
    #pragma unroll
    for (int o = 16; o > 0; o >>= 1) s += __shfl_xor_sync(0xffffffffu, s, o);
    __syncthreads();
    if ((tid & 31) == 0) sh[4 + (tid >> 5)] = s;
    __syncthreads();
    s = sh[4] + sh[5] + sh[6] + sh[7];
    float inv = 1.0f / s;
    #pragma unroll
    for (int i = 0; i < 5; i++) {
        int idx = tid + i * 128;
        if (idx < S_) p[idx] = v[i] * inv;
    }
    // zero the pad columns so pv can read them harmlessly
    if (tid < SP_ - S_) p[S_ + tid] = 0.f;
}

// ---------------- attn = probs @ v : tf32 wmma, out tile 64x64, K=S chunked by 64 ----------------
__global__ __launch_bounds__(128) void pv_kernel(const float* __restrict__ scores,
                                                 const float* __restrict__ qkv,
                                                 float* __restrict__ attn) {
    __shared__ float ps[64 * 68];
    __shared__ float vs[64 * 68];
    __shared__ float stage[4 * 320];
    int bh = blockIdx.z;
    int b = bh / H_, h = bh % H_;
    int it = blockIdx.x;
    int tid = threadIdx.x;
    int wid = tid >> 5, lane = tid & 31;
    int i0 = wid * 16;

    wmma::fragment<wmma::accumulator, 16, 16, 8, float> acc[4];
    #pragma unroll
    for (int j = 0; j < 4; j++) wmma::fill_fragment(acc[j], 0.0f);

    int lr = tid >> 1;
    int lc0 = (tid & 1) * 32;

    for (int t0 = 0; t0 < S_; t0 += 64) {
        // P tile [64 rows i][64 cols t] — rows are SP_-strided (16B aligned)
        {
            int gi = it * 64 + lr;
            const float* prow = &scores[((size_t)bh * S_ + (gi < S_ ? gi : 0)) * SP_];
            bool rok = gi < S_;
            #pragma unroll
            for (int i = 0; i < 8; i++) {
                int c = lc0 + i * 4;
                int gt = t0 + c;
                float4 v;
                if (rok && gt + 3 < SP_) v = *(const float4*)&prow[gt];
                else v = make_float4(0.f, 0.f, 0.f, 0.f);
                *(float4*)&ps[lr * 68 + c] = v;
            }
        }
        // V tile [64 rows t][64 cols e]
        {
            int gt = t0 + lr;
            bool rok = gt < S_;
            const float* vrow = &qkv[((size_t)(b * S_ + (rok ? gt : 0))) * (3 * D_) + 2 * D_ + h * DH_];
            #pragma unroll
            for (int i = 0; i < 8; i++) {
                int c = lc0 + i * 4;
                float4 v = rok ? *(const float4*)&vrow[c] : make_float4(0.f, 0.f, 0.f, 0.f);
                *(float4*)&vs[lr * 68 + c] = v;
            }
        }
        __syncthreads();

        #pragma unroll
        for (int kk = 0; kk < 8; kk++) {
            wmma::fragment<wmma::matrix_a, 16, 16, 8, wmma::precision::tf32, wmma::row_major> af;
            wmma::load_matrix_sync(af, ps + i0 * 68 + kk * 8, 68);
            #pragma unroll
            for (int e = 0; e < af.num_elements; e++) af.x[e] = wmma::__float_to_tf32(af.x[e]);
            #pragma unroll
            for (int j = 0; j < 4; j++) {
                wmma::fragment<wmma::matrix_b, 16, 16, 8, wmma::precision::tf32, wmma::row_major> bf;
                wmma::load_matrix_sync(bf, vs + (kk * 8) * 68 + j * 16, 68);
                #pragma unroll
                for (int e = 0; e < bf.num_elements; e++) bf.x[e] = wmma::__float_to_tf32(bf.x[e]);
                wmma::mma_sync(acc[j], af, bf, acc[j]);
            }
        }
        __syncthreads();
    }

    float* st = stage + wid * 320;
    int r = lane >> 1, c0 = (lane & 1) * 8;
    #pragma unroll
    for (int j = 0; j < 4; j++) {
        wmma::store_matrix_sync(st, acc[j], 20, wmma::mem_row_major);
        __syncwarp();
        int gi = it * 64 + i0 + r;
        if (gi < S_) {
            float* orow = &attn[((size_t)(b * S_ + gi)) * D_ + h * DH_ + j * 16 + c0];
            #pragma unroll
            for (int cc = 0; cc < 8; cc++) orow[cc] = st[r * 20 + c0 + cc];
        }
        __syncwarp();
    }
}

// ---------------- launch ----------------
extern "C" void kernel_launch(void* const* d_in, const int* in_sizes, int n_in,
                              void* d_out, int out_size) {
    const float* x     = (const float*)d_in[0];
    const float* ln1_g = (const float*)d_in[1];
    const float* ln1_b = (const float*)d_in[2];
    const float* Wq    = (const float*)d_in[3];
    const float* bq    = (const float*)d_in[4];
    const float* Wk    = (const float*)d_in[5];
    const float* bk    = (const float*)d_in[6];
    const float* Wv    = (const float*)d_in[7];
    const float* bv    = (const float*)d_in[8];
    const float* Wo    = (const float*)d_in[9];
    const float* bo    = (const float*)d_in[10];
    const float* ln2_g = (const float*)d_in[11];
    const float* ln2_b = (const float*)d_in[12];
    const float* W1    = (const float*)d_in[13];
    const float* b1    = (const float*)d_in[14];
    const float* W2    = (const float*)d_in[15];
    const float* b2    = (const float*)d_in[16];
    float* out = (float*)d_out;

    float* h_p;      cudaGetSymbolAddress((void**)&h_p, g_h);
    float* qkv_p;    cudaGetSymbolAddress((void**)&qkv_p, g_qkv);
    float* scores_p; cudaGetSymbolAddress((void**)&scores_p, g_scores);
    float* attn_p;   cudaGetSymbolAddress((void**)&attn_p, g_attn);
    float* ff_p;     cudaGetSymbolAddress((void**)&ff_p, g_ff);
    float* wqkv_p;   cudaGetSymbolAddress((void**)&wqkv_p, g_wqkv);
    float* bqkv_p;   cudaGetSymbolAddress((void**)&bqkv_p, g_bqkv);

    cudaFuncSetAttribute(sgemm_tc<0>, cudaFuncAttributeMaxDynamicSharedMemorySize, GEMM_SMEM_BYTES);
    cudaFuncSetAttribute(sgemm_tc<1>, cudaFuncAttributeMaxDynamicSharedMemorySize, GEMM_SMEM_BYTES);
    cudaFuncSetAttribute(sgemm_tc<2>, cudaFuncAttributeMaxDynamicSharedMemorySize, GEMM_SMEM_BYTES);

    // 1. pack fused QKV weights
    {
        size_t total = (size_t)D_ * 3 * D_;
        int blocks = (int)((total + 255) / 256);
        pack_qkv_kernel<<<blocks, 256>>>(Wq, Wk, Wv, bq, bk, bv);
    }
    // 2. LN1
    ln_kernel<<<NT_, 256>>>(x, ln1_g, ln1_b, h_p);
    // 3. fused QKV GEMM: [NT,768] x [768,2304]
    {
        dim3 grid(3 * D_ / GBN, (NT_ + GBM - 1) / GBM);
        sgemm_tc<0><<<grid, 256, GEMM_SMEM_BYTES>>>(h_p, wqkv_p, bqkv_p, nullptr, qkv_p, NT_, 3 * D_, D_);
    }
    // 4. scores = q k^T / 8
    {
        dim3 grid((S_ + 63) / 64, (S_ + 63) / 64, B_ * H_);
        score_kernel<<<grid, 128>>>(qkv_p, scores_p);
    }
    // 5. softmax
    softmax_kernel<<<B_ * H_ * S_, 128>>>(scores_p);
    // 6. attn = probs @ v
    {
        dim3 grid((S_ + 63) / 64, 1, B_ * H_);
        pv_kernel<<<grid, 128>>>(scores_p, qkv_p, attn_p);
    }
    // 7. x2 = x + attn @ Wo + bo   -> out
    {
        dim3 grid(D_ / GBN, (NT_ + GBM - 1) / GBM);
        sgemm_tc<2><<<grid, 256, GEMM_SMEM_BYTES>>>(attn_p, Wo, bo, x, out, NT_, D_, D_);
    }
    // 8. LN2 on x2
    ln_kernel<<<NT_, 256>>>(out, ln2_g, ln2_b, h_p);
    // 9. ff = gelu(m @ W1 + b1)
    {
        dim3 grid(FF_ / GBN, (NT_ + GBM - 1) / GBM);
        sgemm_tc<1><<<grid, 256, GEMM_SMEM_BYTES>>>(h_p, W1, b1, nullptr, ff_p, NT_, FF_, D_);
    }
    // 10. out = x2 + ff @ W2 + b2
    {
        dim3 grid(D_ / GBN, (NT_ + GBM - 1) / GBM);
        sgemm_tc<2><<<grid, 256, GEMM_SMEM_BYTES>>>(ff_p, W2, b2, out, out, NT_, D_, FF_);
    }
}